// round 5
// baseline (speedup 1.0000x reference)
#include <cuda_runtime.h>
#include <math.h>

#define BATCH   2
#define SEQ     2048
#define DMODEL  2048
#define NHEADS  16
#define DK      128
#define M_TOT   (BATCH*SEQ)   // 4096

// ---------------- scratch (device globals; no allocation allowed) ----------
__device__ float g_q [M_TOT*DMODEL];
__device__ float g_k [M_TOT*DMODEL];
__device__ float g_v [M_TOT*DMODEL];
__device__ float g_ao[M_TOT*DMODEL];

// ---------------------------------------------------------------------------
// C[M,N] = A[M,K] @ W[N,K]^T (+ bias).  BM=BN=128, BK=16, 256 thr, 8x8 micro.
// Fragment indexing is interleaved (ty+16i / tx+16j) -> conflict-free LDS.
// M,N multiples of 128; K multiple of 16 (true for all our shapes).
// ---------------------------------------------------------------------------
__global__ __launch_bounds__(256, 2)
void sgemm_nt(const float* __restrict__ A, const float* __restrict__ W,
              const float* __restrict__ bias, float* __restrict__ C,
              int Mdim, int Ndim, int Kdim)
{
    __shared__ float As[16][128];
    __shared__ float Bs[16][128];

    const int tid = threadIdx.x;
    const int tx = tid & 15, ty = tid >> 4;
    const int m0 = blockIdx.y * 128;
    const int n0 = blockIdx.x * 128;

    float acc[8][8];
#pragma unroll
    for (int i = 0; i < 8; ++i)
#pragma unroll
        for (int j = 0; j < 8; ++j) acc[i][j] = 0.f;

    for (int k0 = 0; k0 < Kdim; k0 += 16) {
#pragma unroll
        for (int r = 0; r < 2; ++r) {
            int id  = tid + r * 256;
            int row = id >> 2;
            int kq  = (id & 3) * 4;
            float4 av = *(const float4*)(A + (size_t)(m0 + row) * Kdim + k0 + kq);
            As[kq+0][row] = av.x; As[kq+1][row] = av.y;
            As[kq+2][row] = av.z; As[kq+3][row] = av.w;
            float4 bv = *(const float4*)(W + (size_t)(n0 + row) * Kdim + k0 + kq);
            Bs[kq+0][row] = bv.x; Bs[kq+1][row] = bv.y;
            Bs[kq+2][row] = bv.z; Bs[kq+3][row] = bv.w;
        }
        __syncthreads();

#pragma unroll
        for (int k = 0; k < 16; ++k) {
            float a[8], b[8];
#pragma unroll
            for (int i = 0; i < 8; ++i) a[i] = As[k][ty + 16*i];
#pragma unroll
            for (int j = 0; j < 8; ++j) b[j] = Bs[k][tx + 16*j];
#pragma unroll
            for (int i = 0; i < 8; ++i)
#pragma unroll
                for (int j = 0; j < 8; ++j)
                    acc[i][j] = fmaf(a[i], b[j], acc[i][j]);
        }
        __syncthreads();
    }

#pragma unroll
    for (int i = 0; i < 8; ++i) {
        int row = m0 + ty + 16*i;
#pragma unroll
        for (int j = 0; j < 8; ++j) {
            int col = n0 + tx + 16*j;
            float v = acc[i][j];
            if (bias) v += bias[col];
            C[(size_t)row * Ndim + col] = v;
        }
    }
}

// ---------------------------------------------------------------------------
// RoPE on Q and K in [B,S,H*Dk] layout. One thread per (m,h,pair).
// ---------------------------------------------------------------------------
__global__ void rope_kernel(float* __restrict__ q, float* __restrict__ k)
{
    int p = blockIdx.x * blockDim.x + threadIdx.x;
    if (p >= M_TOT * NHEADS * (DK/2)) return;
    int i = p & 63;            // pair index within head (Dk/2 = 64)
    int h = (p >> 6) & 15;
    int m = p >> 10;           // b*SEQ + s
    int s = m & (SEQ - 1);

    // freq = 10000^(-2i/128); ln(10000)/128 = 0.07195578415...
    float freq = expf(-(float)(2*i) * 0.07195578415f);
    float ang  = (float)s * freq;
    float sn, cs;
    sincosf(ang, &sn, &cs);

    size_t base = (size_t)m * DMODEL + h*DK + 2*i;
    float qe = q[base], qo = q[base+1];
    q[base]   = qe*cs - qo*sn;
    q[base+1] = qe*sn + qo*cs;
    float ke = k[base], ko = k[base+1];
    k[base]   = ke*cs - ko*sn;
    k[base+1] = ke*sn + ko*cs;
}

// ---------------------------------------------------------------------------
// Causal flash attention.  BQ=BKV=64, Dk=128. 256 threads (16x16).
// Thread (ty,tx): score rows ty+16i (i<4), score cols tx+16j (j<4),
//                 O cols tx+16u (u<8).  Online softmax via xor-shuffle (row
//                 owned by a single ty -> reductions stay inside 16-lane half).
// ---------------------------------------------------------------------------
#define BQ 64
#define BKV 64
#define QK_PITCH 129   // conflict-free K-fragment reads (stride tx*129 -> bank tx)
#define V_PITCH  132   // 16B-aligned rows for float4 STS; PV reads are stride-1
#define S_PITCH  80    // disjoint bank halves for the two rows per warp

struct AttnSmem {
    float Qs[BQ ][QK_PITCH];
    float Ks[BKV][QK_PITCH];
    float Vs[BKV][V_PITCH];
    float Ss[BQ ][S_PITCH];
};

__global__ __launch_bounds__(256, 1)
void flash_attn(const float* __restrict__ Q, const float* __restrict__ K,
                const float* __restrict__ V, float* __restrict__ O)
{
    extern __shared__ unsigned char smem_raw[];
    AttnSmem& sm = *reinterpret_cast<AttnSmem*>(smem_raw);

    const int tid = threadIdx.x;
    const int tx = tid & 15, ty = tid >> 4;
    const int q0 = blockIdx.x * BQ;
    const int bh = blockIdx.y;
    const int b  = bh >> 4, h = bh & 15;
    const size_t head_base = (size_t)(b * SEQ) * DMODEL + h * DK;

    // Q tile -> smem (coalesced float4 gmem, scalar STS due to odd pitch)
    for (int id = tid; id < BQ * (DK/4); id += 256) {
        int row = id >> 5;
        int c4  = (id & 31) * 4;
        float4 v = *(const float4*)(Q + head_base + (size_t)(q0 + row) * DMODEL + c4);
        sm.Qs[row][c4+0] = v.x; sm.Qs[row][c4+1] = v.y;
        sm.Qs[row][c4+2] = v.z; sm.Qs[row][c4+3] = v.w;
    }

    float o[4][8];
    float mrow[4], lrow[4];
#pragma unroll
    for (int i = 0; i < 4; ++i) {
        mrow[i] = -1e30f; lrow[i] = 0.f;
#pragma unroll
        for (int u = 0; u < 8; ++u) o[i][u] = 0.f;
    }

    const float scale = 0.08838834764831845f;  // 1/sqrt(128)

    for (int k0 = 0; k0 <= q0; k0 += BKV) {
        // K,V tiles -> smem
        for (int id = tid; id < BKV * (DK/4); id += 256) {
            int row = id >> 5;
            int c4  = (id & 31) * 4;
            const float* kp = K + head_base + (size_t)(k0 + row) * DMODEL + c4;
            float4 kv = *(const float4*)kp;
            sm.Ks[row][c4+0] = kv.x; sm.Ks[row][c4+1] = kv.y;
            sm.Ks[row][c4+2] = kv.z; sm.Ks[row][c4+3] = kv.w;
            float4 vv = *(const float4*)(V + head_base + (size_t)(k0 + row) * DMODEL + c4);
            *(float4*)&sm.Vs[row][c4] = vv;
        }
        __syncthreads();

        // S = Q K^T  (4x4 per thread, inner Dk=128)
        float s[4][4];
#pragma unroll
        for (int i = 0; i < 4; ++i)
#pragma unroll
            for (int j = 0; j < 4; ++j) s[i][j] = 0.f;

#pragma unroll 4
        for (int d = 0; d < DK; ++d) {
            float qf[4], kf[4];
#pragma unroll
            for (int i = 0; i < 4; ++i) qf[i] = sm.Qs[ty + 16*i][d];
#pragma unroll
            for (int j = 0; j < 4; ++j) kf[j] = sm.Ks[tx + 16*j][d];
#pragma unroll
            for (int i = 0; i < 4; ++i)
#pragma unroll
                for (int j = 0; j < 4; ++j)
                    s[i][j] = fmaf(qf[i], kf[j], s[i][j]);
        }

        const bool diag = (k0 == q0);   // only the diagonal tile needs masking
#pragma unroll
        for (int i = 0; i < 4; ++i) {
            int rg = q0 + ty + 16*i;
#pragma unroll
            for (int j = 0; j < 4; ++j) {
                int cg = k0 + tx + 16*j;
                s[i][j] = (diag && cg > rg) ? -1e30f : s[i][j] * scale;
            }
        }

        // online softmax update (row reductions via xor shuffle over 16 lanes)
#pragma unroll
        for (int i = 0; i < 4; ++i) {
            float mx = fmaxf(fmaxf(s[i][0], s[i][1]), fmaxf(s[i][2], s[i][3]));
#pragma unroll
            for (int off = 8; off >= 1; off >>= 1)
                mx = fmaxf(mx, __shfl_xor_sync(0xffffffffu, mx, off));
            float mnew  = fmaxf(mrow[i], mx);
            float alpha = __expf(mrow[i] - mnew);
            mrow[i] = mnew;

            float rs = 0.f;
#pragma unroll
            for (int j = 0; j < 4; ++j) {
                float p = __expf(s[i][j] - mnew);
                s[i][j] = p;
                rs += p;
            }
#pragma unroll
            for (int off = 8; off >= 1; off >>= 1)
                rs += __shfl_xor_sync(0xffffffffu, rs, off);
            lrow[i] = lrow[i] * alpha + rs;

#pragma unroll
            for (int u = 0; u < 8; ++u) o[i][u] *= alpha;
#pragma unroll
            for (int j = 0; j < 4; ++j) sm.Ss[ty + 16*i][tx + 16*j] = s[i][j];
        }
        __syncthreads();

        // O += P @ V
#pragma unroll 2
        for (int kk = 0; kk < BKV; ++kk) {
            float vv[8];
#pragma unroll
            for (int u = 0; u < 8; ++u) vv[u] = sm.Vs[kk][tx + 16*u];
#pragma unroll
            for (int i = 0; i < 4; ++i) {
                float p = sm.Ss[ty + 16*i][kk];
#pragma unroll
                for (int u = 0; u < 8; ++u)
                    o[i][u] = fmaf(p, vv[u], o[i][u]);
            }
        }
        __syncthreads();
    }

    // epilogue: normalize and store (coalesced across tx)
#pragma unroll
    for (int i = 0; i < 4; ++i) {
        float inv = 1.f / lrow[i];
        int row = q0 + ty + 16*i;
#pragma unroll
        for (int u = 0; u < 8; ++u)
            O[head_base + (size_t)row * DMODEL + tx + 16*u] = o[i][u] * inv;
    }
}

// ---------------------------------------------------------------------------
extern "C" void kernel_launch(void* const* d_in, const int* in_sizes, int n_in,
                              void* d_out, int out_size)
{
    (void)in_sizes; (void)n_in; (void)out_size;
    const float* x  = (const float*)d_in[0];
    const float* wq = (const float*)d_in[1];
    const float* wk = (const float*)d_in[2];
    const float* wv = (const float*)d_in[3];
    const float* wo = (const float*)d_in[4];
    const float* bo = (const float*)d_in[5];
    float* out = (float*)d_out;

    float *q, *k, *v, *ao;
    cudaGetSymbolAddress((void**)&q,  g_q);
    cudaGetSymbolAddress((void**)&k,  g_k);
    cudaGetSymbolAddress((void**)&v,  g_v);
    cudaGetSymbolAddress((void**)&ao, g_ao);

    dim3 gblk(256);
    dim3 ggrid(DMODEL / 128, M_TOT / 128);  // (16, 32)
    sgemm_nt<<<ggrid, gblk>>>(x, wq, nullptr, q, M_TOT, DMODEL, DMODEL);
    sgemm_nt<<<ggrid, gblk>>>(x, wk, nullptr, k, M_TOT, DMODEL, DMODEL);
    sgemm_nt<<<ggrid, gblk>>>(x, wv, nullptr, v, M_TOT, DMODEL, DMODEL);

    int pairs = M_TOT * NHEADS * (DK/2);
    rope_kernel<<<(pairs + 255) / 256, 256>>>(q, k);

    cudaFuncSetAttribute(flash_attn, cudaFuncAttributeMaxDynamicSharedMemorySize,
                         (int)sizeof(AttnSmem));
    dim3 agrid(SEQ / BQ, BATCH * NHEADS);   // (32, 32)
    flash_attn<<<agrid, 256, sizeof(AttnSmem)>>>(q, k, v, ao);

    sgemm_nt<<<ggrid, gblk>>>(ao, wo, bo, out, M_TOT, DMODEL, DMODEL);
}

// round 12
// speedup vs baseline: 2.1160x; 2.1160x over previous
#include <cuda_runtime.h>
#include <cuda_fp16.h>
#include <math.h>
#include <stdint.h>

#define BATCH   2
#define SEQ     2048
#define DMODEL  2048
#define NHEADS  16
#define DK      128
#define M_TOT   (BATCH*SEQ)   // 4096
#define KX      6144          // 3x expanded K for fp16 split GEMM

// ---------------- fp32 scratch ----------------
__device__ float g_q [M_TOT*DMODEL];
__device__ float g_k [M_TOT*DMODEL];
__device__ float g_v [M_TOT*DMODEL];
__device__ float g_ao[M_TOT*DMODEL];

// ---------------- fp16 3-term expanded operands -----------------------------
__device__ __half g_x3 [(size_t)M_TOT*KX];        // x  -> [Ah,Ah,Al]
__device__ __half g_ao3[(size_t)M_TOT*KX];        // ao -> [Ah,Ah,Al]
__device__ __half g_w3 [(size_t)4*DMODEL*KX];     // w  -> [Wh,Wl,Wh] x4

// ============================ PTX helpers ==================================
__device__ __forceinline__ uint32_t smem_u32(const void* p) {
    uint32_t a;
    asm("{ .reg .u64 t; cvta.to.shared.u64 t, %1; cvt.u32.u64 %0, t; }"
        : "=r"(a) : "l"(p));
    return a;
}
__device__ __forceinline__ void cp_async16(uint32_t dst, const void* src) {
    asm volatile("cp.async.cg.shared.global [%0], [%1], 16;"
                 :: "r"(dst), "l"(src) : "memory");
}
#define CP_COMMIT()  asm volatile("cp.async.commit_group;" ::: "memory")
#define CP_WAIT1()   asm volatile("cp.async.wait_group 1;" ::: "memory")

#define LDSM_X4(r, addr) \
    asm volatile("ldmatrix.sync.aligned.m8n8.x4.shared.b16 {%0,%1,%2,%3}, [%4];" \
        : "=r"((r)[0]), "=r"((r)[1]), "=r"((r)[2]), "=r"((r)[3]) : "r"(addr))

#define MMA16816(d, a, b) \
    asm volatile("mma.sync.aligned.m16n8k16.row.col.f32.f16.f16.f32 " \
        "{%0,%1,%2,%3}, {%4,%5,%6,%7}, {%8,%9}, {%0,%1,%2,%3};" \
        : "+f"((d)[0]), "+f"((d)[1]), "+f"((d)[2]), "+f"((d)[3]) \
        : "r"((a)[0]), "r"((a)[1]), "r"((a)[2]), "r"((a)[3]), \
          "r"((b)[0]), "r"((b)[1]))

// ===========================================================================
// Expansion: fp32 [rows,2048] -> fp16 [rows,6144].
//   act==1:  per k emit (h, h, l)     (activation side)
//   act==0:  per k emit (h, l, h)     (weight side)
// sum_k' A3[k']*W3[k'] = sum_k Ah*Wh + Ah*Wl + Al*Wh   (exact 3-term split)
// One thread: 4 source k -> 12 output halves (3x 8B stores, 8B-aligned).
// ===========================================================================
__global__ void conv_expand(const float* __restrict__ src,
                            __half* __restrict__ dst, int act)
{
    int p   = blockIdx.x * blockDim.x + threadIdx.x;
    int row = p >> 9;                 // 512 quads per row
    int kq  = (p & 511) * 4;

    float4 v = *(const float4*)(src + ((size_t)row << 11) + kq);
    float f[4] = {v.x, v.y, v.z, v.w};
    __half h[4], l[4];
#pragma unroll
    for (int i = 0; i < 4; ++i) {
        h[i] = __float2half_rn(f[i]);
        l[i] = __float2half_rn(f[i] - __half2float(h[i]));
    }

    __half o[12];
    if (act) {
#pragma unroll
        for (int i = 0; i < 4; ++i) { o[3*i] = h[i]; o[3*i+1] = h[i]; o[3*i+2] = l[i]; }
    } else {
#pragma unroll
        for (int i = 0; i < 4; ++i) { o[3*i] = h[i]; o[3*i+1] = l[i]; o[3*i+2] = h[i]; }
    }

    uint2* d = (uint2*)(dst + (size_t)row * KX + (size_t)kq * 3);
    const uint2* s2 = (const uint2*)o;
    d[0] = s2[0]; d[1] = s2[1]; d[2] = s2[2];
}

// ===========================================================================
// fp16 mma.sync GEMM: C[4096,2048] = A3[4096,KX] @ W3[2048,KX]^T (+bias).
// BM=BN=128, BK=64 halves; 8 warps (2M x 4N), warp tile 64x32.
// 3-stage cp.async pipeline; 16B-chunk XOR swizzle; ldmatrix.x4 fragments.
// ===========================================================================
#define GKT      (KX/64)     // 96 k-tiles
#define STAGES   3
#define STG_B    32768u      // A(16KB) + B(16KB) per stage
#define GEMM_SMEM (STAGES*STG_B)

__global__ __launch_bounds__(256, 2)
void gemm_mma(const __half* __restrict__ A3, const __half* __restrict__ W3,
              const float* __restrict__ bias, float* __restrict__ C)
{
    extern __shared__ unsigned char smraw[];
    const uint32_t sbase = smem_u32(smraw);

    const int tid  = threadIdx.x;
    const int lane = tid & 31, wid = tid >> 5;
    const int wm = wid & 1, wn = wid >> 1;          // 2 x 4 warp grid
    const int m0 = blockIdx.y * 128, n0 = blockIdx.x * 128;

    // cp.async indices: 256 thr -> 32 rows x 8 chunks per pass, 4 passes/tile
    const int ldr = tid >> 3;          // row 0..31
    const int ldc = tid & 7;           // 16B chunk 0..7
    const __half* agp = A3 + (size_t)(m0 + ldr) * KX + ldc * 8;
    const __half* wgp = W3 + (size_t)(n0 + ldr) * KX + ldc * 8;
    const uint32_t sw_off = (uint32_t)(ldr * 8 + (ldc ^ (ldr & 7))) * 16;

    float acc[4][4][4];
#pragma unroll
    for (int mi = 0; mi < 4; ++mi)
#pragma unroll
        for (int ni = 0; ni < 4; ++ni)
#pragma unroll
            for (int r = 0; r < 4; ++r) acc[mi][ni][r] = 0.f;

    // precomputed ldmatrix address offsets (swizzled), per k-step recompute chunk
    // A: lane -> row wm*64 + mi*16 + (lane&15), chunk-bit lane>>4
    // B: lane -> row wn*32 + nj*16 + (lane&7) + ((lane>>4)<<3), chunk-bit (lane>>3)&1
    const int arow = wm * 64 + (lane & 15);
    const int acb  = lane >> 4;
    const int brow = wn * 32 + (lane & 7) + ((lane >> 4) << 3);
    const int bcb  = (lane >> 3) & 1;

    auto load_stage = [&](int slot, int kt) {
        uint32_t s = sbase + (uint32_t)slot * STG_B;
        const __half* ag = agp + (size_t)kt * 64;
        const __half* wg = wgp + (size_t)kt * 64;
#pragma unroll
        for (int r4 = 0; r4 < 4; ++r4) {
            uint32_t o = sw_off + (uint32_t)r4 * 32 * 128;   // +32 rows
            cp_async16(s + o,          ag + (size_t)r4 * 32 * KX);
            cp_async16(s + 16384u + o, wg + (size_t)r4 * 32 * KX);
        }
    };

    auto compute_stage = [&](int slot) {
        uint32_t s  = sbase + (uint32_t)slot * STG_B;
        uint32_t sb = s + 16384u;
#pragma unroll
        for (int ks = 0; ks < 4; ++ks) {
            uint32_t a[4][4], b[4][2];
#pragma unroll
            for (int mi = 0; mi < 4; ++mi) {
                int row = arow + mi * 16;
                uint32_t addr = s + (uint32_t)(row * 8 + ((2*ks + acb) ^ (row & 7))) * 16;
                LDSM_X4(a[mi], addr);
            }
#pragma unroll
            for (int nj = 0; nj < 2; ++nj) {
                int row = brow + nj * 16;
                uint32_t addr = sb + (uint32_t)(row * 8 + ((2*ks + bcb) ^ (row & 7))) * 16;
                uint32_t r[4];
                LDSM_X4(r, addr);
                b[nj*2+0][0] = r[0]; b[nj*2+0][1] = r[1];
                b[nj*2+1][0] = r[2]; b[nj*2+1][1] = r[3];
            }
#pragma unroll
            for (int mi = 0; mi < 4; ++mi)
#pragma unroll
                for (int ni = 0; ni < 4; ++ni)
                    MMA16816(acc[mi][ni], a[mi], b[ni]);
        }
    };

    load_stage(0, 0); CP_COMMIT();
    load_stage(1, 1); CP_COMMIT();

    for (int kt = 0; kt < GKT; ++kt) {
        CP_WAIT1();
        __syncthreads();
        int pf = kt + STAGES - 1;
        if (pf < GKT) { load_stage(pf % STAGES, pf); CP_COMMIT(); }
        compute_stage(kt % STAGES);
    }

    // epilogue: m16n8k16 D-frag layout -> C
#pragma unroll
    for (int mi = 0; mi < 4; ++mi) {
        int row = m0 + wm * 64 + mi * 16 + (lane >> 2);
#pragma unroll
        for (int ni = 0; ni < 4; ++ni) {
            int col = n0 + wn * 32 + ni * 8 + (lane & 3) * 2;
            float2 v0 = {acc[mi][ni][0], acc[mi][ni][1]};
            float2 v1 = {acc[mi][ni][2], acc[mi][ni][3]};
            if (bias) {
                float b0 = __ldg(bias + col), b1 = __ldg(bias + col + 1);
                v0.x += b0; v0.y += b1; v1.x += b0; v1.y += b1;
            }
            *(float2*)(C + (size_t) row      * DMODEL + col) = v0;
            *(float2*)(C + (size_t)(row + 8) * DMODEL + col) = v1;
        }
    }
}

// ---------------------------------------------------------------------------
// RoPE (unchanged, known-correct)
// ---------------------------------------------------------------------------
__global__ void rope_kernel(float* __restrict__ q, float* __restrict__ k)
{
    int p = blockIdx.x * blockDim.x + threadIdx.x;
    if (p >= M_TOT * NHEADS * (DK/2)) return;
    int i = p & 63;
    int h = (p >> 6) & 15;
    int m = p >> 10;
    int s = m & (SEQ - 1);

    float freq = expf(-(float)(2*i) * 0.07195578415f);
    float ang  = (float)s * freq;
    float sn, cs;
    sincosf(ang, &sn, &cs);

    size_t base = (size_t)m * DMODEL + h*DK + 2*i;
    float qe = q[base], qo = q[base+1];
    q[base]   = qe*cs - qo*sn;
    q[base+1] = qe*sn + qo*cs;
    float ke = k[base], ko = k[base+1];
    k[base]   = ke*cs - ko*sn;
    k[base+1] = ke*sn + ko*cs;
}

// ---------------------------------------------------------------------------
// Causal flash attention (unchanged, known-correct from R5)
// ---------------------------------------------------------------------------
#define BQ 64
#define BKV 64
#define QK_PITCH 129
#define V_PITCH  132
#define S_PITCH  80

struct AttnSmem {
    float Qs[BQ ][QK_PITCH];
    float Ks[BKV][QK_PITCH];
    float Vs[BKV][V_PITCH];
    float Ss[BQ ][S_PITCH];
};

__global__ __launch_bounds__(256, 1)
void flash_attn(const float* __restrict__ Q, const float* __restrict__ K,
                const float* __restrict__ V, float* __restrict__ O)
{
    extern __shared__ unsigned char smem_raw[];
    AttnSmem& sm = *reinterpret_cast<AttnSmem*>(smem_raw);

    const int tid = threadIdx.x;
    const int tx = tid & 15, ty = tid >> 4;
    const int q0 = blockIdx.x * BQ;
    const int bh = blockIdx.y;
    const int b  = bh >> 4, h = bh & 15;
    const size_t head_base = (size_t)(b * SEQ) * DMODEL + h * DK;

    for (int id = tid; id < BQ * (DK/4); id += 256) {
        int row = id >> 5;
        int c4  = (id & 31) * 4;
        float4 v = *(const float4*)(Q + head_base + (size_t)(q0 + row) * DMODEL + c4);
        sm.Qs[row][c4+0] = v.x; sm.Qs[row][c4+1] = v.y;
        sm.Qs[row][c4+2] = v.z; sm.Qs[row][c4+3] = v.w;
    }

    float o[4][8];
    float mrow[4], lrow[4];
#pragma unroll
    for (int i = 0; i < 4; ++i) {
        mrow[i] = -1e30f; lrow[i] = 0.f;
#pragma unroll
        for (int u = 0; u < 8; ++u) o[i][u] = 0.f;
    }

    const float scale = 0.08838834764831845f;

    for (int k0 = 0; k0 <= q0; k0 += BKV) {
        for (int id = tid; id < BKV * (DK/4); id += 256) {
            int row = id >> 5;
            int c4  = (id & 31) * 4;
            const float* kp = K + head_base + (size_t)(k0 + row) * DMODEL + c4;
            float4 kv = *(const float4*)kp;
            sm.Ks[row][c4+0] = kv.x; sm.Ks[row][c4+1] = kv.y;
            sm.Ks[row][c4+2] = kv.z; sm.Ks[row][c4+3] = kv.w;
            float4 vv = *(const float4*)(V + head_base + (size_t)(k0 + row) * DMODEL + c4);
            *(float4*)&sm.Vs[row][c4] = vv;
        }
        __syncthreads();

        float s[4][4];
#pragma unroll
        for (int i = 0; i < 4; ++i)
#pragma unroll
            for (int j = 0; j < 4; ++j) s[i][j] = 0.f;

#pragma unroll 4
        for (int d = 0; d < DK; ++d) {
            float qf[4], kf[4];
#pragma unroll
            for (int i = 0; i < 4; ++i) qf[i] = sm.Qs[ty + 16*i][d];
#pragma unroll
            for (int j = 0; j < 4; ++j) kf[j] = sm.Ks[tx + 16*j][d];
#pragma unroll
            for (int i = 0; i < 4; ++i)
#pragma unroll
                for (int j = 0; j < 4; ++j)
                    s[i][j] = fmaf(qf[i], kf[j], s[i][j]);
        }

        const bool diag = (k0 == q0);
#pragma unroll
        for (int i = 0; i < 4; ++i) {
            int rg = q0 + ty + 16*i;
#pragma unroll
            for (int j = 0; j < 4; ++j) {
                int cg = k0 + tx + 16*j;
                s[i][j] = (diag && cg > rg) ? -1e30f : s[i][j] * scale;
            }
        }

#pragma unroll
        for (int i = 0; i < 4; ++i) {
            float mx = fmaxf(fmaxf(s[i][0], s[i][1]), fmaxf(s[i][2], s[i][3]));
#pragma unroll
            for (int off = 8; off >= 1; off >>= 1)
                mx = fmaxf(mx, __shfl_xor_sync(0xffffffffu, mx, off));
            float mnew  = fmaxf(mrow[i], mx);
            float alpha = __expf(mrow[i] - mnew);
            mrow[i] = mnew;

            float rs = 0.f;
#pragma unroll
            for (int j = 0; j < 4; ++j) {
                float p = __expf(s[i][j] - mnew);
                s[i][j] = p;
                rs += p;
            }
#pragma unroll
            for (int off = 8; off >= 1; off >>= 1)
                rs += __shfl_xor_sync(0xffffffffu, rs, off);
            lrow[i] = lrow[i] * alpha + rs;

#pragma unroll
            for (int u = 0; u < 8; ++u) o[i][u] *= alpha;
#pragma unroll
            for (int j = 0; j < 4; ++j) sm.Ss[ty + 16*i][tx + 16*j] = s[i][j];
        }
        __syncthreads();

#pragma unroll 2
        for (int kk = 0; kk < BKV; ++kk) {
            float vv[8];
#pragma unroll
            for (int u = 0; u < 8; ++u) vv[u] = sm.Vs[kk][tx + 16*u];
#pragma unroll
            for (int i = 0; i < 4; ++i) {
                float p = sm.Ss[ty + 16*i][kk];
#pragma unroll
                for (int u = 0; u < 8; ++u)
                    o[i][u] = fmaf(p, vv[u], o[i][u]);
            }
        }
        __syncthreads();
    }

#pragma unroll
    for (int i = 0; i < 4; ++i) {
        float inv = 1.f / lrow[i];
        int row = q0 + ty + 16*i;
#pragma unroll
        for (int u = 0; u < 8; ++u)
            O[head_base + (size_t)row * DMODEL + tx + 16*u] = o[i][u] * inv;
    }
}

// ---------------------------------------------------------------------------
extern "C" void kernel_launch(void* const* d_in, const int* in_sizes, int n_in,
                              void* d_out, int out_size)
{
    (void)in_sizes; (void)n_in; (void)out_size;
    const float* x  = (const float*)d_in[0];
    const float* wq = (const float*)d_in[1];
    const float* wk = (const float*)d_in[2];
    const float* wv = (const float*)d_in[3];
    const float* wo = (const float*)d_in[4];
    const float* bo = (const float*)d_in[5];
    float* out = (float*)d_out;

    float *q, *k, *v, *ao;
    __half *x3, *ao3, *w3;
    cudaGetSymbolAddress((void**)&q,   g_q);
    cudaGetSymbolAddress((void**)&k,   g_k);
    cudaGetSymbolAddress((void**)&v,   g_v);
    cudaGetSymbolAddress((void**)&ao,  g_ao);
    cudaGetSymbolAddress((void**)&x3,  g_x3);
    cudaGetSymbolAddress((void**)&ao3, g_ao3);
    cudaGetSymbolAddress((void**)&w3,  g_w3);

    const size_t W3SZ = (size_t)DMODEL * KX;

    // expand operands (act: h,h,l ; weight: h,l,h)
    conv_expand<<<(M_TOT*512)/256, 256>>>(x,  x3, 1);
    conv_expand<<<(DMODEL*512)/256, 256>>>(wq, w3 + 0*W3SZ, 0);
    conv_expand<<<(DMODEL*512)/256, 256>>>(wk, w3 + 1*W3SZ, 0);
    conv_expand<<<(DMODEL*512)/256, 256>>>(wv, w3 + 2*W3SZ, 0);
    conv_expand<<<(DMODEL*512)/256, 256>>>(wo, w3 + 3*W3SZ, 0);

    cudaFuncSetAttribute(gemm_mma, cudaFuncAttributeMaxDynamicSharedMemorySize,
                         (int)GEMM_SMEM);
    dim3 ggrid(DMODEL/128, M_TOT/128);   // (16, 32)
    gemm_mma<<<ggrid, 256, GEMM_SMEM>>>(x3, w3 + 0*W3SZ, nullptr, q);
    gemm_mma<<<ggrid, 256, GEMM_SMEM>>>(x3, w3 + 1*W3SZ, nullptr, k);
    gemm_mma<<<ggrid, 256, GEMM_SMEM>>>(x3, w3 + 2*W3SZ, nullptr, v);

    int pairs = M_TOT * NHEADS * (DK/2);
    rope_kernel<<<(pairs + 255) / 256, 256>>>(q, k);

    cudaFuncSetAttribute(flash_attn, cudaFuncAttributeMaxDynamicSharedMemorySize,
                         (int)sizeof(AttnSmem));
    dim3 agrid(SEQ / BQ, BATCH * NHEADS);
    flash_attn<<<agrid, 256, sizeof(AttnSmem)>>>(q, k, v, ao);

    conv_expand<<<(M_TOT*512)/256, 256>>>(ao, ao3, 1);
    gemm_mma<<<ggrid, 256, GEMM_SMEM>>>(ao3, w3 + 3*W3SZ, bo, out);
}

// round 13
// speedup vs baseline: 3.3749x; 1.5950x over previous
#include <cuda_runtime.h>
#include <cuda_fp16.h>
#include <math.h>
#include <stdint.h>

#define BATCH   2
#define SEQ     2048
#define DMODEL  2048
#define NHEADS  16
#define DK      128
#define M_TOT   (BATCH*SEQ)   // 4096
#define KX      6144          // 3x expanded K for fp16 split GEMM

// ---------------- fp32 scratch ----------------
__device__ float g_q [M_TOT*DMODEL];
__device__ float g_k [M_TOT*DMODEL];
__device__ float g_v [M_TOT*DMODEL];
__device__ float g_ao[M_TOT*DMODEL];

// ---------------- fp16 3-term expanded operands (projection GEMMs) ---------
__device__ __half g_x3 [(size_t)M_TOT*KX];
__device__ __half g_ao3[(size_t)M_TOT*KX];
__device__ __half g_w3 [(size_t)4*DMODEL*KX];

// ---------------- fp16 split operands for attention ------------------------
__device__ __half g_qh [M_TOT*DMODEL];
__device__ __half g_ql [M_TOT*DMODEL];
__device__ __half g_kh [M_TOT*DMODEL];
__device__ __half g_kl [M_TOT*DMODEL];
__device__ __half g_vth[M_TOT*DMODEL];   // [b,h,d,s]
__device__ __half g_vtl[M_TOT*DMODEL];   // [b,h,d,s]

// ============================ PTX helpers ==================================
__device__ __forceinline__ uint32_t smem_u32(const void* p) {
    uint32_t a;
    asm("{ .reg .u64 t; cvta.to.shared.u64 t, %1; cvt.u32.u64 %0, t; }"
        : "=r"(a) : "l"(p));
    return a;
}
__device__ __forceinline__ void cp_async16(uint32_t dst, const void* src) {
    asm volatile("cp.async.cg.shared.global [%0], [%1], 16;"
                 :: "r"(dst), "l"(src) : "memory");
}
#define CP_COMMIT()  asm volatile("cp.async.commit_group;" ::: "memory")
#define CP_WAIT1()   asm volatile("cp.async.wait_group 1;" ::: "memory")
#define CP_WAIT0()   asm volatile("cp.async.wait_group 0;" ::: "memory")

#define LDSM_X4(r, addr) \
    asm volatile("ldmatrix.sync.aligned.m8n8.x4.shared.b16 {%0,%1,%2,%3}, [%4];" \
        : "=r"((r)[0]), "=r"((r)[1]), "=r"((r)[2]), "=r"((r)[3]) : "r"(addr))

#define MMA16816(d, a, b) \
    asm volatile("mma.sync.aligned.m16n8k16.row.col.f32.f16.f16.f32 " \
        "{%0,%1,%2,%3}, {%4,%5,%6,%7}, {%8,%9}, {%0,%1,%2,%3};" \
        : "+f"((d)[0]), "+f"((d)[1]), "+f"((d)[2]), "+f"((d)[3]) \
        : "r"((a)[0]), "r"((a)[1]), "r"((a)[2]), "r"((a)[3]), \
          "r"((b)[0]), "r"((b)[1]))

// ===========================================================================
// Expansion for projection GEMMs (unchanged, verified)
// ===========================================================================
__global__ void conv_expand(const float* __restrict__ src,
                            __half* __restrict__ dst, int act)
{
    int p   = blockIdx.x * blockDim.x + threadIdx.x;
    int row = p >> 9;
    int kq  = (p & 511) * 4;

    float4 v = *(const float4*)(src + ((size_t)row << 11) + kq);
    float f[4] = {v.x, v.y, v.z, v.w};
    __half h[4], l[4];
#pragma unroll
    for (int i = 0; i < 4; ++i) {
        h[i] = __float2half_rn(f[i]);
        l[i] = __float2half_rn(f[i] - __half2float(h[i]));
    }

    __half o[12];
    if (act) {
#pragma unroll
        for (int i = 0; i < 4; ++i) { o[3*i] = h[i]; o[3*i+1] = h[i]; o[3*i+2] = l[i]; }
    } else {
#pragma unroll
        for (int i = 0; i < 4; ++i) { o[3*i] = h[i]; o[3*i+1] = l[i]; o[3*i+2] = h[i]; }
    }

    uint2* d = (uint2*)(dst + (size_t)row * KX + (size_t)kq * 3);
    const uint2* s2 = (const uint2*)o;
    d[0] = s2[0]; d[1] = s2[1]; d[2] = s2[2];
}

// ===========================================================================
// fp16 mma.sync projection GEMM (unchanged, verified in R12)
// ===========================================================================
#define GKT      (KX/64)
#define STAGES   3
#define STG_B    32768u
#define GEMM_SMEM (STAGES*STG_B)

__global__ __launch_bounds__(256, 2)
void gemm_mma(const __half* __restrict__ A3, const __half* __restrict__ W3,
              const float* __restrict__ bias, float* __restrict__ C)
{
    extern __shared__ unsigned char smraw[];
    const uint32_t sbase = smem_u32(smraw);

    const int tid  = threadIdx.x;
    const int lane = tid & 31, wid = tid >> 5;
    const int wm = wid & 1, wn = wid >> 1;
    const int m0 = blockIdx.y * 128, n0 = blockIdx.x * 128;

    const int ldr = tid >> 3;
    const int ldc = tid & 7;
    const __half* agp = A3 + (size_t)(m0 + ldr) * KX + ldc * 8;
    const __half* wgp = W3 + (size_t)(n0 + ldr) * KX + ldc * 8;
    const uint32_t sw_off = (uint32_t)(ldr * 8 + (ldc ^ (ldr & 7))) * 16;

    float acc[4][4][4];
#pragma unroll
    for (int mi = 0; mi < 4; ++mi)
#pragma unroll
        for (int ni = 0; ni < 4; ++ni)
#pragma unroll
            for (int r = 0; r < 4; ++r) acc[mi][ni][r] = 0.f;

    const int arow = wm * 64 + (lane & 15);
    const int acb  = lane >> 4;
    const int brow = wn * 32 + (lane & 7) + ((lane >> 4) << 3);
    const int bcb  = (lane >> 3) & 1;

    auto load_stage = [&](int slot, int kt) {
        uint32_t s = sbase + (uint32_t)slot * STG_B;
        const __half* ag = agp + (size_t)kt * 64;
        const __half* wg = wgp + (size_t)kt * 64;
#pragma unroll
        for (int r4 = 0; r4 < 4; ++r4) {
            uint32_t o = sw_off + (uint32_t)r4 * 32 * 128;
            cp_async16(s + o,          ag + (size_t)r4 * 32 * KX);
            cp_async16(s + 16384u + o, wg + (size_t)r4 * 32 * KX);
        }
    };

    auto compute_stage = [&](int slot) {
        uint32_t s  = sbase + (uint32_t)slot * STG_B;
        uint32_t sb = s + 16384u;
#pragma unroll
        for (int ks = 0; ks < 4; ++ks) {
            uint32_t a[4][4], b[4][2];
#pragma unroll
            for (int mi = 0; mi < 4; ++mi) {
                int row = arow + mi * 16;
                uint32_t addr = s + (uint32_t)(row * 8 + ((2*ks + acb) ^ (row & 7))) * 16;
                LDSM_X4(a[mi], addr);
            }
#pragma unroll
            for (int nj = 0; nj < 2; ++nj) {
                int row = brow + nj * 16;
                uint32_t addr = sb + (uint32_t)(row * 8 + ((2*ks + bcb) ^ (row & 7))) * 16;
                uint32_t r[4];
                LDSM_X4(r, addr);
                b[nj*2+0][0] = r[0]; b[nj*2+0][1] = r[1];
                b[nj*2+1][0] = r[2]; b[nj*2+1][1] = r[3];
            }
#pragma unroll
            for (int mi = 0; mi < 4; ++mi)
#pragma unroll
                for (int ni = 0; ni < 4; ++ni)
                    MMA16816(acc[mi][ni], a[mi], b[ni]);
        }
    };

    load_stage(0, 0); CP_COMMIT();
    load_stage(1, 1); CP_COMMIT();

    for (int kt = 0; kt < GKT; ++kt) {
        CP_WAIT1();
        __syncthreads();
        int pf = kt + STAGES - 1;
        if (pf < GKT) { load_stage(pf % STAGES, pf); CP_COMMIT(); }
        compute_stage(kt % STAGES);
    }

#pragma unroll
    for (int mi = 0; mi < 4; ++mi) {
        int row = m0 + wm * 64 + mi * 16 + (lane >> 2);
#pragma unroll
        for (int ni = 0; ni < 4; ++ni) {
            int col = n0 + wn * 32 + ni * 8 + (lane & 3) * 2;
            float2 v0 = {acc[mi][ni][0], acc[mi][ni][1]};
            float2 v1 = {acc[mi][ni][2], acc[mi][ni][3]};
            if (bias) {
                float b0 = __ldg(bias + col), b1 = __ldg(bias + col + 1);
                v0.x += b0; v0.y += b1; v1.x += b0; v1.y += b1;
            }
            *(float2*)(C + (size_t) row      * DMODEL + col) = v0;
            *(float2*)(C + (size_t)(row + 8) * DMODEL + col) = v1;
        }
    }
}

// ---------------------------------------------------------------------------
// RoPE (unchanged)
// ---------------------------------------------------------------------------
__global__ void rope_kernel(float* __restrict__ q, float* __restrict__ k)
{
    int p = blockIdx.x * blockDim.x + threadIdx.x;
    if (p >= M_TOT * NHEADS * (DK/2)) return;
    int i = p & 63;
    int h = (p >> 6) & 15;
    int m = p >> 10;
    int s = m & (SEQ - 1);

    float freq = expf(-(float)(2*i) * 0.07195578415f);
    float ang  = (float)s * freq;
    float sn, cs;
    sincosf(ang, &sn, &cs);

    size_t base = (size_t)m * DMODEL + h*DK + 2*i;
    float qe = q[base], qo = q[base+1];
    q[base]   = qe*cs - qo*sn;
    q[base+1] = qe*sn + qo*cs;
    float ke = k[base], ko = k[base+1];
    k[base]   = ke*cs - ko*sn;
    k[base+1] = ke*sn + ko*cs;
}

// ---------------------------------------------------------------------------
// Elementwise hi/lo split (q, k)
// ---------------------------------------------------------------------------
__global__ void split_hl(const float* __restrict__ src,
                         __half* __restrict__ hi, __half* __restrict__ lo)
{
    size_t p = (size_t)(blockIdx.x * blockDim.x + threadIdx.x) * 4;
    float4 v = *(const float4*)(src + p);
    float f[4] = {v.x, v.y, v.z, v.w};
    __half hh[4], ll[4];
#pragma unroll
    for (int i = 0; i < 4; ++i) {
        hh[i] = __float2half_rn(f[i]);
        ll[i] = __float2half_rn(f[i] - __half2float(hh[i]));
    }
    *(uint2*)(hi + p) = *(uint2*)hh;
    *(uint2*)(lo + p) = *(uint2*)ll;
}

// ---------------------------------------------------------------------------
// V transpose + split: v[b,s,h*128+d] -> vth/vtl[(bh*128+d)*2048 + s]
// Block: (s-block 64) x (bh).  Smem-tiled to keep both sides coalesced.
// ---------------------------------------------------------------------------
__global__ void vt_split(const float* __restrict__ v,
                         __half* __restrict__ vth, __half* __restrict__ vtl)
{
    __shared__ float sm[64][129];
    int s0 = blockIdx.x * 64;
    int bh = blockIdx.y;
    int b  = bh >> 4, h = bh & 15;
    const float* src = v + (size_t)(b*SEQ)*DMODEL + h*DK;

    for (int i = threadIdx.x; i < 64*32; i += 256) {
        int r = i >> 5, c4 = (i & 31) * 4;
        float4 vv = *(const float4*)(src + (size_t)(s0 + r) * DMODEL + c4);
        sm[r][c4] = vv.x; sm[r][c4+1] = vv.y; sm[r][c4+2] = vv.z; sm[r][c4+3] = vv.w;
    }
    __syncthreads();

    int d  = threadIdx.x >> 1;
    int j0 = (threadIdx.x & 1) * 32;
    size_t obase = ((size_t)bh * DK + d) * SEQ + s0 + j0;
#pragma unroll
    for (int jj = 0; jj < 32; jj += 8) {
        __half hh[8], ll[8];
#pragma unroll
        for (int u = 0; u < 8; ++u) {
            float f = sm[j0 + jj + u][d];
            __half x = __float2half_rn(f);
            hh[u] = x;
            ll[u] = __float2half_rn(f - __half2float(x));
        }
        *(uint4*)(vth + obase + jj) = *(uint4*)hh;
        *(uint4*)(vtl + obase + jj) = *(uint4*)ll;
    }
}

// ===========================================================================
// mma.sync causal flash attention with 3-term fp16 split everywhere.
// BQ=128 (8 warps x 16 rows), BKV=64, Dk=128.
// Smem: Qh|Ql (64KB) + 2 KV stages (Kh|Kl|Vth|Vtl, 64KB each) = 192 KB.
// ===========================================================================
#define ABQ   128
#define ABKV  64
#define AQH_O 0u
#define AQL_O 32768u
#define AKV_O 65536u
#define AKV_STG 65536u
#define AKH_O 0u
#define AKL_O 16384u
#define AVH_O 32768u
#define AVL_O 49152u
#define ATTN_SMEM (65536u + 2u*65536u)

__global__ __launch_bounds__(256, 1)
void flash_attn_mma(const __half* __restrict__ qh, const __half* __restrict__ ql,
                    const __half* __restrict__ kh, const __half* __restrict__ kl,
                    const __half* __restrict__ vth, const __half* __restrict__ vtl,
                    float* __restrict__ Og)
{
    extern __shared__ unsigned char smraw[];
    const uint32_t sb = smem_u32(smraw);
    const int tid = threadIdx.x, lane = tid & 31, wid = tid >> 5;
    const int qblk = gridDim.x - 1 - blockIdx.x;     // long CTAs first
    const int q0 = qblk * ABQ;
    const int bh = blockIdx.y;
    const int b  = bh >> 4, h = bh & 15;
    const size_t qk_base = (size_t)(b*SEQ)*DMODEL + h*DK;   // halves
    const size_t vt_base = (size_t)bh * DK * SEQ;           // halves

    const int ntiles = q0 / ABKV + 2;
    const int g = lane >> 2, t4 = lane & 3;
    const int wq0 = q0 + wid * 16;

    // ---- Q tiles (group with KV tile 0) ----
    {
        int c  = tid & 15;
        int r0 = tid >> 4;
#pragma unroll
        for (int rr = 0; rr < 8; ++rr) {
            int row = r0 + rr * 16;
            uint32_t dst = (uint32_t)(row * 16 + (c ^ (row & 7))) * 16;
            const __half* gq = qh + qk_base + (size_t)(q0 + row) * DMODEL + c * 8;
            cp_async16(sb + AQH_O + dst, gq);
            const __half* gq2 = ql + qk_base + (size_t)(q0 + row) * DMODEL + c * 8;
            cp_async16(sb + AQL_O + dst, gq2);
        }
    }
    auto load_kv = [&](int st, int tl) {
        uint32_t s = sb + AKV_O + (uint32_t)st * AKV_STG;
        int k0 = tl * ABKV;
        {   // K: 64 rows x 16 chunks, both arrays
            int c  = tid & 15;
            int r0 = tid >> 4;
#pragma unroll
            for (int rr = 0; rr < 4; ++rr) {
                int row = r0 + rr * 16;
                uint32_t dst = (uint32_t)(row * 16 + (c ^ (row & 7))) * 16;
                cp_async16(s + AKH_O + dst,
                           kh + qk_base + (size_t)(k0 + row) * DMODEL + c * 8);
                cp_async16(s + AKL_O + dst,
                           kl + qk_base + (size_t)(k0 + row) * DMODEL + c * 8);
            }
        }
        {   // Vt: 128 d-rows x 8 chunks, both arrays
            int c  = tid & 7;
            int r0 = tid >> 3;
#pragma unroll
            for (int rr = 0; rr < 4; ++rr) {
                int row = r0 + rr * 32;
                uint32_t dst = (uint32_t)(row * 8 + (c ^ (row & 7))) * 16;
                cp_async16(s + AVH_O + dst,
                           vth + vt_base + (size_t)row * SEQ + k0 + c * 8);
                cp_async16(s + AVL_O + dst,
                           vtl + vt_base + (size_t)row * SEQ + k0 + c * 8);
            }
        }
    };

    load_kv(0, 0); CP_COMMIT();

    float o[16][4];
#pragma unroll
    for (int nt = 0; nt < 16; ++nt)
#pragma unroll
        for (int r = 0; r < 4; ++r) o[nt][r] = 0.f;
    float m0 = -1e30f, m1 = -1e30f, den0 = 0.f, den1 = 0.f;
    const float scale = 0.08838834764831845f;   // 1/sqrt(128)

    for (int tl = 0; tl < ntiles; ++tl) {
        int k0 = tl * ABKV;
        if (tl + 1 < ntiles) { load_kv((tl + 1) & 1, tl + 1); CP_COMMIT(); CP_WAIT1(); }
        else                 { CP_WAIT0(); }
        __syncthreads();

        uint32_t st = sb + AKV_O + (uint32_t)(tl & 1) * AKV_STG;

        if (k0 <= wq0 + 15) {           // warp has at least one unmasked col
            // ---------------- S = Q K^T (3-pass split) ----------------
            float s4[8][4];
#pragma unroll
            for (int nt = 0; nt < 8; ++nt)
#pragma unroll
                for (int r = 0; r < 4; ++r) s4[nt][r] = 0.f;

#pragma unroll
            for (int pass = 0; pass < 3; ++pass) {
                uint32_t aB = sb + (pass == 2 ? AQL_O : AQH_O);
                uint32_t bB = st + (pass == 1 ? AKL_O : AKH_O);
#pragma unroll
                for (int ks = 0; ks < 8; ++ks) {
                    uint32_t a[4];
                    int arow = wid * 16 + (lane & 15);
                    int ach  = 2 * ks + (lane >> 4);
                    LDSM_X4(a, aB + (uint32_t)(arow * 16 + (ach ^ (arow & 7))) * 16);
#pragma unroll
                    for (int nj = 0; nj < 4; ++nj) {
                        int brow = (lane & 7) + ((lane >> 4) << 3) + nj * 16;
                        int bch  = 2 * ks + ((lane >> 3) & 1);
                        uint32_t r[4];
                        LDSM_X4(r, bB + (uint32_t)(brow * 16 + (bch ^ (brow & 7))) * 16);
                        uint32_t b0[2] = {r[0], r[1]}, b1[2] = {r[2], r[3]};
                        MMA16816(s4[2*nj],   a, b0);
                        MMA16816(s4[2*nj+1], a, b1);
                    }
                }
            }

            // ---------------- scale + causal mask ----------------
            const bool domask = (k0 + ABKV - 1 > wq0);
            const int r0g = wq0 + g, r1g = wq0 + 8 + g;
#pragma unroll
            for (int nt = 0; nt < 8; ++nt) {
#pragma unroll
                for (int r = 0; r < 4; ++r) s4[nt][r] *= scale;
                if (domask) {
                    int c0 = k0 + nt * 8 + 2 * t4;
                    if (c0     > r0g) s4[nt][0] = -1e30f;
                    if (c0 + 1 > r0g) s4[nt][1] = -1e30f;
                    if (c0     > r1g) s4[nt][2] = -1e30f;
                    if (c0 + 1 > r1g) s4[nt][3] = -1e30f;
                }
            }

            // ---------------- online softmax ----------------
            float mx0 = -1e30f, mx1 = -1e30f;
#pragma unroll
            for (int nt = 0; nt < 8; ++nt) {
                mx0 = fmaxf(mx0, fmaxf(s4[nt][0], s4[nt][1]));
                mx1 = fmaxf(mx1, fmaxf(s4[nt][2], s4[nt][3]));
            }
            mx0 = fmaxf(mx0, __shfl_xor_sync(0xffffffffu, mx0, 1));
            mx0 = fmaxf(mx0, __shfl_xor_sync(0xffffffffu, mx0, 2));
            mx1 = fmaxf(mx1, __shfl_xor_sync(0xffffffffu, mx1, 1));
            mx1 = fmaxf(mx1, __shfl_xor_sync(0xffffffffu, mx1, 2));
            float mn0 = fmaxf(m0, mx0), mn1 = fmaxf(m1, mx1);
            float al0 = __expf(m0 - mn0), al1 = __expf(m1 - mn1);
            m0 = mn0; m1 = mn1;

            float sum0 = 0.f, sum1 = 0.f;
            uint32_t phA[8], phB[8], plA[8], plB[8];
#pragma unroll
            for (int nt = 0; nt < 8; ++nt) {
                float e0 = __expf(s4[nt][0] - mn0), e1 = __expf(s4[nt][1] - mn0);
                float e2 = __expf(s4[nt][2] - mn1), e3 = __expf(s4[nt][3] - mn1);
                sum0 += e0 + e1; sum1 += e2 + e3;
                __half2 h0 = __floats2half2_rn(e0, e1);
                __half2 h1 = __floats2half2_rn(e2, e3);
                float2 f0 = __half22float2(h0), f1 = __half22float2(h1);
                __half2 q0h = __floats2half2_rn(e0 - f0.x, e1 - f0.y);
                __half2 q1h = __floats2half2_rn(e2 - f1.x, e3 - f1.y);
                phA[nt] = *(uint32_t*)&h0;  phB[nt] = *(uint32_t*)&h1;
                plA[nt] = *(uint32_t*)&q0h; plB[nt] = *(uint32_t*)&q1h;
            }
            sum0 += __shfl_xor_sync(0xffffffffu, sum0, 1);
            sum0 += __shfl_xor_sync(0xffffffffu, sum0, 2);
            sum1 += __shfl_xor_sync(0xffffffffu, sum1, 1);
            sum1 += __shfl_xor_sync(0xffffffffu, sum1, 2);
            den0 = den0 * al0 + sum0;
            den1 = den1 * al1 + sum1;

#pragma unroll
            for (int nt = 0; nt < 16; ++nt) {
                o[nt][0] *= al0; o[nt][1] *= al0;
                o[nt][2] *= al1; o[nt][3] *= al1;
            }

            // ---------------- O += P V (3-pass split) ----------------
#pragma unroll
            for (int pass = 0; pass < 3; ++pass) {
                uint32_t vB = st + (pass == 1 ? AVL_O : AVH_O);
#pragma unroll
                for (int ks = 0; ks < 4; ++ks) {
                    uint32_t a[4];
                    if (pass == 2) {
                        a[0] = plA[2*ks]; a[1] = plB[2*ks];
                        a[2] = plA[2*ks+1]; a[3] = plB[2*ks+1];
                    } else {
                        a[0] = phA[2*ks]; a[1] = phB[2*ks];
                        a[2] = phA[2*ks+1]; a[3] = phB[2*ks+1];
                    }
#pragma unroll
                    for (int nj = 0; nj < 8; ++nj) {
                        int brow = (lane & 7) + ((lane >> 4) << 3) + nj * 16;
                        int bch  = 2 * ks + ((lane >> 3) & 1);
                        uint32_t r[4];
                        LDSM_X4(r, vB + (uint32_t)(brow * 8 + (bch ^ (brow & 7))) * 16);
                        uint32_t b0[2] = {r[0], r[1]}, b1[2] = {r[2], r[3]};
                        MMA16816(o[2*nj],   a, b0);
                        MMA16816(o[2*nj+1], a, b1);
                    }
                }
            }
        }
        __syncthreads();
    }

    // ---------------- epilogue ----------------
    float inv0 = 1.f / den0, inv1 = 1.f / den1;
    int row0 = wq0 + g;
    float* O0 = Og + (size_t)(b*SEQ + row0) * DMODEL + h * DK;
    float* O1 = O0 + (size_t)8 * DMODEL;
#pragma unroll
    for (int nt = 0; nt < 16; ++nt) {
        int col = nt * 8 + 2 * t4;
        float2 v0 = {o[nt][0] * inv0, o[nt][1] * inv0};
        float2 v1 = {o[nt][2] * inv1, o[nt][3] * inv1};
        *(float2*)(O0 + col) = v0;
        *(float2*)(O1 + col) = v1;
    }
}

// ---------------------------------------------------------------------------
extern "C" void kernel_launch(void* const* d_in, const int* in_sizes, int n_in,
                              void* d_out, int out_size)
{
    (void)in_sizes; (void)n_in; (void)out_size;
    const float* x  = (const float*)d_in[0];
    const float* wq = (const float*)d_in[1];
    const float* wk = (const float*)d_in[2];
    const float* wv = (const float*)d_in[3];
    const float* wo = (const float*)d_in[4];
    const float* bo = (const float*)d_in[5];
    float* out = (float*)d_out;

    float *q, *k, *v, *ao;
    __half *x3, *ao3, *w3, *qh, *ql, *kh, *kl, *vth, *vtl;
    cudaGetSymbolAddress((void**)&q,   g_q);
    cudaGetSymbolAddress((void**)&k,   g_k);
    cudaGetSymbolAddress((void**)&v,   g_v);
    cudaGetSymbolAddress((void**)&ao,  g_ao);
    cudaGetSymbolAddress((void**)&x3,  g_x3);
    cudaGetSymbolAddress((void**)&ao3, g_ao3);
    cudaGetSymbolAddress((void**)&w3,  g_w3);
    cudaGetSymbolAddress((void**)&qh,  g_qh);
    cudaGetSymbolAddress((void**)&ql,  g_ql);
    cudaGetSymbolAddress((void**)&kh,  g_kh);
    cudaGetSymbolAddress((void**)&kl,  g_kl);
    cudaGetSymbolAddress((void**)&vth, g_vth);
    cudaGetSymbolAddress((void**)&vtl, g_vtl);

    const size_t W3SZ = (size_t)DMODEL * KX;

    conv_expand<<<(M_TOT*512)/256, 256>>>(x,  x3, 1);
    conv_expand<<<(DMODEL*512)/256, 256>>>(wq, w3 + 0*W3SZ, 0);
    conv_expand<<<(DMODEL*512)/256, 256>>>(wk, w3 + 1*W3SZ, 0);
    conv_expand<<<(DMODEL*512)/256, 256>>>(wv, w3 + 2*W3SZ, 0);
    conv_expand<<<(DMODEL*512)/256, 256>>>(wo, w3 + 3*W3SZ, 0);

    cudaFuncSetAttribute(gemm_mma, cudaFuncAttributeMaxDynamicSharedMemorySize,
                         (int)GEMM_SMEM);
    dim3 ggrid(DMODEL/128, M_TOT/128);
    gemm_mma<<<ggrid, 256, GEMM_SMEM>>>(x3, w3 + 0*W3SZ, nullptr, q);
    gemm_mma<<<ggrid, 256, GEMM_SMEM>>>(x3, w3 + 1*W3SZ, nullptr, k);
    gemm_mma<<<ggrid, 256, GEMM_SMEM>>>(x3, w3 + 2*W3SZ, nullptr, v);

    int pairs = M_TOT * NHEADS * (DK/2);
    rope_kernel<<<(pairs + 255) / 256, 256>>>(q, k);

    // split q/k, transpose+split v
    int quads = M_TOT * DMODEL / 4;
    split_hl<<<quads/256, 256>>>(q, qh, ql);
    split_hl<<<quads/256, 256>>>(k, kh, kl);
    vt_split<<<dim3(SEQ/64, BATCH*NHEADS), 256>>>(v, vth, vtl);

    cudaFuncSetAttribute(flash_attn_mma, cudaFuncAttributeMaxDynamicSharedMemorySize,
                         (int)ATTN_SMEM);
    dim3 agrid(SEQ/ABQ, BATCH*NHEADS);   // (16, 32)
    flash_attn_mma<<<agrid, 256, ATTN_SMEM>>>(qh, ql, kh, kl, vth, vtl, ao);

    conv_expand<<<(M_TOT*512)/256, 256>>>(ao, ao3, 1);
    gemm_mma<<<ggrid, 256, GEMM_SMEM>>>(ao3, w3 + 3*W3SZ, bo, out);
}

// round 14
// speedup vs baseline: 3.9419x; 1.1680x over previous
#include <cuda_runtime.h>
#include <cuda_fp16.h>
#include <math.h>
#include <stdint.h>

#define BATCH   2
#define SEQ     2048
#define DMODEL  2048
#define NHEADS  16
#define DK      128
#define M_TOT   (BATCH*SEQ)   // 4096
#define KX      6144          // 3x expanded K for fp16 split GEMM

// ---------------- fp32 scratch ----------------
__device__ float g_q [M_TOT*DMODEL];
__device__ float g_k [M_TOT*DMODEL];
__device__ float g_v [M_TOT*DMODEL];
__device__ float g_ao[M_TOT*DMODEL];

// ---------------- fp16 3-term expanded operands (projection GEMMs) ---------
__device__ __half g_x3 [(size_t)M_TOT*KX];
__device__ __half g_ao3[(size_t)M_TOT*KX];
__device__ __half g_w3 [(size_t)4*DMODEL*KX];

// ---------------- fp16 split operands for attention ------------------------
__device__ __half g_qh [M_TOT*DMODEL];
__device__ __half g_ql [M_TOT*DMODEL];
__device__ __half g_kh [M_TOT*DMODEL];
__device__ __half g_kl [M_TOT*DMODEL];
__device__ __half g_vth[M_TOT*DMODEL];   // [b,h,d,s]
__device__ __half g_vtl[M_TOT*DMODEL];   // [b,h,d,s]

// ============================ PTX helpers ==================================
__device__ __forceinline__ uint32_t smem_u32(const void* p) {
    uint32_t a;
    asm("{ .reg .u64 t; cvta.to.shared.u64 t, %1; cvt.u32.u64 %0, t; }"
        : "=r"(a) : "l"(p));
    return a;
}
__device__ __forceinline__ void cp_async16(uint32_t dst, const void* src) {
    asm volatile("cp.async.cg.shared.global [%0], [%1], 16;"
                 :: "r"(dst), "l"(src) : "memory");
}
#define CP_COMMIT()  asm volatile("cp.async.commit_group;" ::: "memory")
#define CP_WAIT1()   asm volatile("cp.async.wait_group 1;" ::: "memory")
#define CP_WAIT0()   asm volatile("cp.async.wait_group 0;" ::: "memory")

#define LDSM_X4(r, addr) \
    asm volatile("ldmatrix.sync.aligned.m8n8.x4.shared.b16 {%0,%1,%2,%3}, [%4];" \
        : "=r"((r)[0]), "=r"((r)[1]), "=r"((r)[2]), "=r"((r)[3]) : "r"(addr))

#define MMA16816(d, a, b) \
    asm volatile("mma.sync.aligned.m16n8k16.row.col.f32.f16.f16.f32 " \
        "{%0,%1,%2,%3}, {%4,%5,%6,%7}, {%8,%9}, {%0,%1,%2,%3};" \
        : "+f"((d)[0]), "+f"((d)[1]), "+f"((d)[2]), "+f"((d)[3]) \
        : "r"((a)[0]), "r"((a)[1]), "r"((a)[2]), "r"((a)[3]), \
          "r"((b)[0]), "r"((b)[1]))

// ===========================================================================
// Expansion for projection GEMMs (unchanged, verified)
// ===========================================================================
__global__ void conv_expand(const float* __restrict__ src,
                            __half* __restrict__ dst, int act)
{
    int p   = blockIdx.x * blockDim.x + threadIdx.x;
    int row = p >> 9;
    int kq  = (p & 511) * 4;

    float4 v = *(const float4*)(src + ((size_t)row << 11) + kq);
    float f[4] = {v.x, v.y, v.z, v.w};
    __half h[4], l[4];
#pragma unroll
    for (int i = 0; i < 4; ++i) {
        h[i] = __float2half_rn(f[i]);
        l[i] = __float2half_rn(f[i] - __half2float(h[i]));
    }

    __half o[12];
    if (act) {
#pragma unroll
        for (int i = 0; i < 4; ++i) { o[3*i] = h[i]; o[3*i+1] = h[i]; o[3*i+2] = l[i]; }
    } else {
#pragma unroll
        for (int i = 0; i < 4; ++i) { o[3*i] = h[i]; o[3*i+1] = l[i]; o[3*i+2] = h[i]; }
    }

    uint2* d = (uint2*)(dst + (size_t)row * KX + (size_t)kq * 3);
    const uint2* s2 = (const uint2*)o;
    d[0] = s2[0]; d[1] = s2[1]; d[2] = s2[2];
}

// ===========================================================================
// fp16 mma.sync GEMM over N-concatenated outputs.
// C index n0 selects output buffer: sel = n0>>11 -> C0/C1/C2, col = n0&2047.
// Body identical to verified R12/R13 kernel.
// ===========================================================================
#define GKT      (KX/64)
#define STAGES   3
#define STG_B    32768u
#define GEMM_SMEM (STAGES*STG_B)

__global__ __launch_bounds__(256, 2)
void gemm_mma(const __half* __restrict__ A3, const __half* __restrict__ W3,
              const float* __restrict__ bias,
              float* __restrict__ C0, float* __restrict__ C1,
              float* __restrict__ C2)
{
    extern __shared__ unsigned char smraw[];
    const uint32_t sbase = smem_u32(smraw);

    const int tid  = threadIdx.x;
    const int lane = tid & 31, wid = tid >> 5;
    const int wm = wid & 1, wn = wid >> 1;
    const int m0 = blockIdx.y * 128, n0 = blockIdx.x * 128;

    const int ldr = tid >> 3;
    const int ldc = tid & 7;
    const __half* agp = A3 + (size_t)(m0 + ldr) * KX + ldc * 8;
    const __half* wgp = W3 + (size_t)(n0 + ldr) * KX + ldc * 8;
    const uint32_t sw_off = (uint32_t)(ldr * 8 + (ldc ^ (ldr & 7))) * 16;

    float acc[4][4][4];
#pragma unroll
    for (int mi = 0; mi < 4; ++mi)
#pragma unroll
        for (int ni = 0; ni < 4; ++ni)
#pragma unroll
            for (int r = 0; r < 4; ++r) acc[mi][ni][r] = 0.f;

    const int arow = wm * 64 + (lane & 15);
    const int acb  = lane >> 4;
    const int brow = wn * 32 + (lane & 7) + ((lane >> 4) << 3);
    const int bcb  = (lane >> 3) & 1;

    auto load_stage = [&](int slot, int kt) {
        uint32_t s = sbase + (uint32_t)slot * STG_B;
        const __half* ag = agp + (size_t)kt * 64;
        const __half* wg = wgp + (size_t)kt * 64;
#pragma unroll
        for (int r4 = 0; r4 < 4; ++r4) {
            uint32_t o = sw_off + (uint32_t)r4 * 32 * 128;
            cp_async16(s + o,          ag + (size_t)r4 * 32 * KX);
            cp_async16(s + 16384u + o, wg + (size_t)r4 * 32 * KX);
        }
    };

    auto compute_stage = [&](int slot) {
        uint32_t s  = sbase + (uint32_t)slot * STG_B;
        uint32_t sb = s + 16384u;
#pragma unroll
        for (int ks = 0; ks < 4; ++ks) {
            uint32_t a[4][4], b[4][2];
#pragma unroll
            for (int mi = 0; mi < 4; ++mi) {
                int row = arow + mi * 16;
                uint32_t addr = s + (uint32_t)(row * 8 + ((2*ks + acb) ^ (row & 7))) * 16;
                LDSM_X4(a[mi], addr);
            }
#pragma unroll
            for (int nj = 0; nj < 2; ++nj) {
                int row = brow + nj * 16;
                uint32_t addr = sb + (uint32_t)(row * 8 + ((2*ks + bcb) ^ (row & 7))) * 16;
                uint32_t r[4];
                LDSM_X4(r, addr);
                b[nj*2+0][0] = r[0]; b[nj*2+0][1] = r[1];
                b[nj*2+1][0] = r[2]; b[nj*2+1][1] = r[3];
            }
#pragma unroll
            for (int mi = 0; mi < 4; ++mi)
#pragma unroll
                for (int ni = 0; ni < 4; ++ni)
                    MMA16816(acc[mi][ni], a[mi], b[ni]);
        }
    };

    load_stage(0, 0); CP_COMMIT();
    load_stage(1, 1); CP_COMMIT();

    for (int kt = 0; kt < GKT; ++kt) {
        CP_WAIT1();
        __syncthreads();
        int pf = kt + STAGES - 1;
        if (pf < GKT) { load_stage(pf % STAGES, pf); CP_COMMIT(); }
        compute_stage(kt % STAGES);
    }

    const int sel = n0 >> 11;
    float* Cx = (sel == 0) ? C0 : ((sel == 1) ? C1 : C2);
    const int nc0 = n0 & (DMODEL - 1);

#pragma unroll
    for (int mi = 0; mi < 4; ++mi) {
        int row = m0 + wm * 64 + mi * 16 + (lane >> 2);
#pragma unroll
        for (int ni = 0; ni < 4; ++ni) {
            int col = nc0 + wn * 32 + ni * 8 + (lane & 3) * 2;
            float2 v0 = {acc[mi][ni][0], acc[mi][ni][1]};
            float2 v1 = {acc[mi][ni][2], acc[mi][ni][3]};
            if (bias) {
                float b0 = __ldg(bias + col), b1 = __ldg(bias + col + 1);
                v0.x += b0; v0.y += b1; v1.x += b0; v1.y += b1;
            }
            *(float2*)(Cx + (size_t) row      * DMODEL + col) = v0;
            *(float2*)(Cx + (size_t)(row + 8) * DMODEL + col) = v1;
        }
    }
}

// ---------------------------------------------------------------------------
// Fused RoPE + hi/lo split: reads fp32 q,k; writes qh/ql/kh/kl directly.
// One thread per (m,h,pair); pair elements are adjacent -> half2 stores.
// ---------------------------------------------------------------------------
__global__ void rope_split(const float* __restrict__ q, const float* __restrict__ k,
                           __half* __restrict__ qh, __half* __restrict__ ql,
                           __half* __restrict__ kh, __half* __restrict__ kl)
{
    int p = blockIdx.x * blockDim.x + threadIdx.x;
    if (p >= M_TOT * NHEADS * (DK/2)) return;
    int i = p & 63;
    int h = (p >> 6) & 15;
    int m = p >> 10;
    int s = m & (SEQ - 1);

    float freq = expf(-(float)(2*i) * 0.07195578415f);
    float ang  = (float)s * freq;
    float sn, cs;
    sincosf(ang, &sn, &cs);

    size_t base = (size_t)m * DMODEL + h*DK + 2*i;
    float2 qv = *(const float2*)(q + base);
    float2 kv = *(const float2*)(k + base);
    float q0 = qv.x*cs - qv.y*sn, q1 = qv.x*sn + qv.y*cs;
    float k0 = kv.x*cs - kv.y*sn, k1 = kv.x*sn + kv.y*cs;

    __half2 qhh = __floats2half2_rn(q0, q1);
    float2  qhf = __half22float2(qhh);
    __half2 qll = __floats2half2_rn(q0 - qhf.x, q1 - qhf.y);
    __half2 khh = __floats2half2_rn(k0, k1);
    float2  khf = __half22float2(khh);
    __half2 kll = __floats2half2_rn(k0 - khf.x, k1 - khf.y);

    *(__half2*)(qh + base) = qhh;
    *(__half2*)(ql + base) = qll;
    *(__half2*)(kh + base) = khh;
    *(__half2*)(kl + base) = kll;
}

// ---------------------------------------------------------------------------
// V transpose + split (unchanged, verified)
// ---------------------------------------------------------------------------
__global__ void vt_split(const float* __restrict__ v,
                         __half* __restrict__ vth, __half* __restrict__ vtl)
{
    __shared__ float sm[64][129];
    int s0 = blockIdx.x * 64;
    int bh = blockIdx.y;
    int b  = bh >> 4, h = bh & 15;
    const float* src = v + (size_t)(b*SEQ)*DMODEL + h*DK;

    for (int i = threadIdx.x; i < 64*32; i += 256) {
        int r = i >> 5, c4 = (i & 31) * 4;
        float4 vv = *(const float4*)(src + (size_t)(s0 + r) * DMODEL + c4);
        sm[r][c4] = vv.x; sm[r][c4+1] = vv.y; sm[r][c4+2] = vv.z; sm[r][c4+3] = vv.w;
    }
    __syncthreads();

    int d  = threadIdx.x >> 1;
    int j0 = (threadIdx.x & 1) * 32;
    size_t obase = ((size_t)bh * DK + d) * SEQ + s0 + j0;
#pragma unroll
    for (int jj = 0; jj < 32; jj += 8) {
        __half hh[8], ll[8];
#pragma unroll
        for (int u = 0; u < 8; ++u) {
            float f = sm[j0 + jj + u][d];
            __half x = __float2half_rn(f);
            hh[u] = x;
            ll[u] = __float2half_rn(f - __half2float(x));
        }
        *(uint4*)(vth + obase + jj) = *(uint4*)hh;
        *(uint4*)(vtl + obase + jj) = *(uint4*)ll;
    }
}

// ===========================================================================
// mma.sync causal flash attention, fragment-reuse inner loops.
// BQ=128 (8 warps x 16 rows), BKV=64, Dk=128.  Smem 192 KB.
// ===========================================================================
#define ABQ   128
#define ABKV  64
#define AQH_O 0u
#define AQL_O 32768u
#define AKV_O 65536u
#define AKV_STG 65536u
#define AKH_O 0u
#define AKL_O 16384u
#define AVH_O 32768u
#define AVL_O 49152u
#define ATTN_SMEM (65536u + 2u*65536u)

__global__ __launch_bounds__(256, 1)
void flash_attn_mma(const __half* __restrict__ qh, const __half* __restrict__ ql,
                    const __half* __restrict__ kh, const __half* __restrict__ kl,
                    const __half* __restrict__ vth, const __half* __restrict__ vtl,
                    float* __restrict__ Og)
{
    extern __shared__ unsigned char smraw[];
    const uint32_t sb = smem_u32(smraw);
    const int tid = threadIdx.x, lane = tid & 31, wid = tid >> 5;
    const int qblk = gridDim.x - 1 - blockIdx.x;
    const int q0 = qblk * ABQ;
    const int bh = blockIdx.y;
    const int b  = bh >> 4, h = bh & 15;
    const size_t qk_base = (size_t)(b*SEQ)*DMODEL + h*DK;
    const size_t vt_base = (size_t)bh * DK * SEQ;

    const int ntiles = q0 / ABKV + 2;
    const int g = lane >> 2, t4 = lane & 3;
    const int wq0 = q0 + wid * 16;

    {   // Q tiles
        int c  = tid & 15;
        int r0 = tid >> 4;
#pragma unroll
        for (int rr = 0; rr < 8; ++rr) {
            int row = r0 + rr * 16;
            uint32_t dst = (uint32_t)(row * 16 + (c ^ (row & 7))) * 16;
            cp_async16(sb + AQH_O + dst,
                       qh + qk_base + (size_t)(q0 + row) * DMODEL + c * 8);
            cp_async16(sb + AQL_O + dst,
                       ql + qk_base + (size_t)(q0 + row) * DMODEL + c * 8);
        }
    }
    auto load_kv = [&](int st, int tl) {
        uint32_t s = sb + AKV_O + (uint32_t)st * AKV_STG;
        int k0 = tl * ABKV;
        {
            int c  = tid & 15;
            int r0 = tid >> 4;
#pragma unroll
            for (int rr = 0; rr < 4; ++rr) {
                int row = r0 + rr * 16;
                uint32_t dst = (uint32_t)(row * 16 + (c ^ (row & 7))) * 16;
                cp_async16(s + AKH_O + dst,
                           kh + qk_base + (size_t)(k0 + row) * DMODEL + c * 8);
                cp_async16(s + AKL_O + dst,
                           kl + qk_base + (size_t)(k0 + row) * DMODEL + c * 8);
            }
        }
        {
            int c  = tid & 7;
            int r0 = tid >> 3;
#pragma unroll
            for (int rr = 0; rr < 4; ++rr) {
                int row = r0 + rr * 32;
                uint32_t dst = (uint32_t)(row * 8 + (c ^ (row & 7))) * 16;
                cp_async16(s + AVH_O + dst,
                           vth + vt_base + (size_t)row * SEQ + k0 + c * 8);
                cp_async16(s + AVL_O + dst,
                           vtl + vt_base + (size_t)row * SEQ + k0 + c * 8);
            }
        }
    };

    load_kv(0, 0); CP_COMMIT();

    float o[16][4];
#pragma unroll
    for (int nt = 0; nt < 16; ++nt)
#pragma unroll
        for (int r = 0; r < 4; ++r) o[nt][r] = 0.f;
    float m0 = -1e30f, m1 = -1e30f, den0 = 0.f, den1 = 0.f;
    const float scale = 0.08838834764831845f;

    for (int tl = 0; tl < ntiles; ++tl) {
        int k0 = tl * ABKV;
        if (tl + 1 < ntiles) { load_kv((tl + 1) & 1, tl + 1); CP_COMMIT(); CP_WAIT1(); }
        else                 { CP_WAIT0(); }
        __syncthreads();

        uint32_t st = sb + AKV_O + (uint32_t)(tl & 1) * AKV_STG;

        if (k0 <= wq0 + 15) {
            // -------- S = Q K^T, fragment-reuse: load QH/QL + KH/KL once/ks --
            float s4[8][4];
#pragma unroll
            for (int nt = 0; nt < 8; ++nt)
#pragma unroll
                for (int r = 0; r < 4; ++r) s4[nt][r] = 0.f;

            const int arow = wid * 16 + (lane & 15);
            const int brow0 = (lane & 7) + ((lane >> 4) << 3);
            const int bcbit = (lane >> 3) & 1;
#pragma unroll
            for (int ks = 0; ks < 8; ++ks) {
                int ach = 2 * ks + (lane >> 4);
                uint32_t qoff = (uint32_t)(arow * 16 + (ach ^ (arow & 7))) * 16;
                uint32_t aH[4], aL[4];
                LDSM_X4(aH, sb + AQH_O + qoff);
                LDSM_X4(aL, sb + AQL_O + qoff);
#pragma unroll
                for (int nj = 0; nj < 4; ++nj) {
                    int brow = brow0 + nj * 16;
                    int bch  = 2 * ks + bcbit;
                    uint32_t koff = (uint32_t)(brow * 16 + (bch ^ (brow & 7))) * 16;
                    uint32_t rH[4], rL[4];
                    LDSM_X4(rH, st + AKH_O + koff);
                    LDSM_X4(rL, st + AKL_O + koff);
                    uint32_t bH0[2] = {rH[0], rH[1]}, bH1[2] = {rH[2], rH[3]};
                    uint32_t bL0[2] = {rL[0], rL[1]}, bL1[2] = {rL[2], rL[3]};
                    MMA16816(s4[2*nj],   aH, bH0);
                    MMA16816(s4[2*nj+1], aH, bH1);
                    MMA16816(s4[2*nj],   aH, bL0);
                    MMA16816(s4[2*nj+1], aH, bL1);
                    MMA16816(s4[2*nj],   aL, bH0);
                    MMA16816(s4[2*nj+1], aL, bH1);
                }
            }

            // -------- scale + causal mask --------
            const bool domask = (k0 + ABKV - 1 > wq0);
            const int r0g = wq0 + g, r1g = wq0 + 8 + g;
#pragma unroll
            for (int nt = 0; nt < 8; ++nt) {
#pragma unroll
                for (int r = 0; r < 4; ++r) s4[nt][r] *= scale;
                if (domask) {
                    int c0 = k0 + nt * 8 + 2 * t4;
                    if (c0     > r0g) s4[nt][0] = -1e30f;
                    if (c0 + 1 > r0g) s4[nt][1] = -1e30f;
                    if (c0     > r1g) s4[nt][2] = -1e30f;
                    if (c0 + 1 > r1g) s4[nt][3] = -1e30f;
                }
            }

            // -------- online softmax --------
            float mx0 = -1e30f, mx1 = -1e30f;
#pragma unroll
            for (int nt = 0; nt < 8; ++nt) {
                mx0 = fmaxf(mx0, fmaxf(s4[nt][0], s4[nt][1]));
                mx1 = fmaxf(mx1, fmaxf(s4[nt][2], s4[nt][3]));
            }
            mx0 = fmaxf(mx0, __shfl_xor_sync(0xffffffffu, mx0, 1));
            mx0 = fmaxf(mx0, __shfl_xor_sync(0xffffffffu, mx0, 2));
            mx1 = fmaxf(mx1, __shfl_xor_sync(0xffffffffu, mx1, 1));
            mx1 = fmaxf(mx1, __shfl_xor_sync(0xffffffffu, mx1, 2));
            float mn0 = fmaxf(m0, mx0), mn1 = fmaxf(m1, mx1);
            float al0 = __expf(m0 - mn0), al1 = __expf(m1 - mn1);
            m0 = mn0; m1 = mn1;

            float sum0 = 0.f, sum1 = 0.f;
            uint32_t phA[8], phB[8], plA[8], plB[8];
#pragma unroll
            for (int nt = 0; nt < 8; ++nt) {
                float e0 = __expf(s4[nt][0] - mn0), e1 = __expf(s4[nt][1] - mn0);
                float e2 = __expf(s4[nt][2] - mn1), e3 = __expf(s4[nt][3] - mn1);
                sum0 += e0 + e1; sum1 += e2 + e3;
                __half2 h0 = __floats2half2_rn(e0, e1);
                __half2 h1 = __floats2half2_rn(e2, e3);
                float2 f0 = __half22float2(h0), f1 = __half22float2(h1);
                __half2 q0h = __floats2half2_rn(e0 - f0.x, e1 - f0.y);
                __half2 q1h = __floats2half2_rn(e2 - f1.x, e3 - f1.y);
                phA[nt] = *(uint32_t*)&h0;  phB[nt] = *(uint32_t*)&h1;
                plA[nt] = *(uint32_t*)&q0h; plB[nt] = *(uint32_t*)&q1h;
            }
            sum0 += __shfl_xor_sync(0xffffffffu, sum0, 1);
            sum0 += __shfl_xor_sync(0xffffffffu, sum0, 2);
            sum1 += __shfl_xor_sync(0xffffffffu, sum1, 1);
            sum1 += __shfl_xor_sync(0xffffffffu, sum1, 2);
            den0 = den0 * al0 + sum0;
            den1 = den1 * al1 + sum1;

#pragma unroll
            for (int nt = 0; nt < 16; ++nt) {
                o[nt][0] *= al0; o[nt][1] *= al0;
                o[nt][2] *= al1; o[nt][3] *= al1;
            }

            // -------- O += P V, fragment-reuse: load VH/VL once/(ks,nj) -----
#pragma unroll
            for (int ks = 0; ks < 4; ++ks) {
                uint32_t aH[4] = {phA[2*ks], phB[2*ks], phA[2*ks+1], phB[2*ks+1]};
                uint32_t aL[4] = {plA[2*ks], plB[2*ks], plA[2*ks+1], plB[2*ks+1]};
#pragma unroll
                for (int nj = 0; nj < 8; ++nj) {
                    int brow = brow0 + nj * 16;
                    int bch  = 2 * ks + bcbit;
                    uint32_t voff = (uint32_t)(brow * 8 + (bch ^ (brow & 7))) * 16;
                    uint32_t rH[4], rL[4];
                    LDSM_X4(rH, st + AVH_O + voff);
                    LDSM_X4(rL, st + AVL_O + voff);
                    uint32_t bH0[2] = {rH[0], rH[1]}, bH1[2] = {rH[2], rH[3]};
                    uint32_t bL0[2] = {rL[0], rL[1]}, bL1[2] = {rL[2], rL[3]};
                    MMA16816(o[2*nj],   aH, bH0);
                    MMA16816(o[2*nj+1], aH, bH1);
                    MMA16816(o[2*nj],   aH, bL0);
                    MMA16816(o[2*nj+1], aH, bL1);
                    MMA16816(o[2*nj],   aL, bH0);
                    MMA16816(o[2*nj+1], aL, bH1);
                }
            }
        }
        __syncthreads();
    }

    // -------- epilogue --------
    float inv0 = 1.f / den0, inv1 = 1.f / den1;
    int row0 = wq0 + g;
    float* O0 = Og + (size_t)(b*SEQ + row0) * DMODEL + h * DK;
    float* O1 = O0 + (size_t)8 * DMODEL;
#pragma unroll
    for (int nt = 0; nt < 16; ++nt) {
        int col = nt * 8 + 2 * t4;
        float2 v0 = {o[nt][0] * inv0, o[nt][1] * inv0};
        float2 v1 = {o[nt][2] * inv1, o[nt][3] * inv1};
        *(float2*)(O0 + col) = v0;
        *(float2*)(O1 + col) = v1;
    }
}

// ---------------------------------------------------------------------------
extern "C" void kernel_launch(void* const* d_in, const int* in_sizes, int n_in,
                              void* d_out, int out_size)
{
    (void)in_sizes; (void)n_in; (void)out_size;
    const float* x  = (const float*)d_in[0];
    const float* wq = (const float*)d_in[1];
    const float* wk = (const float*)d_in[2];
    const float* wv = (const float*)d_in[3];
    const float* wo = (const float*)d_in[4];
    const float* bo = (const float*)d_in[5];
    float* out = (float*)d_out;

    float *q, *k, *v, *ao;
    __half *x3, *ao3, *w3, *qh, *ql, *kh, *kl, *vth, *vtl;
    cudaGetSymbolAddress((void**)&q,   g_q);
    cudaGetSymbolAddress((void**)&k,   g_k);
    cudaGetSymbolAddress((void**)&v,   g_v);
    cudaGetSymbolAddress((void**)&ao,  g_ao);
    cudaGetSymbolAddress((void**)&x3,  g_x3);
    cudaGetSymbolAddress((void**)&ao3, g_ao3);
    cudaGetSymbolAddress((void**)&w3,  g_w3);
    cudaGetSymbolAddress((void**)&qh,  g_qh);
    cudaGetSymbolAddress((void**)&ql,  g_ql);
    cudaGetSymbolAddress((void**)&kh,  g_kh);
    cudaGetSymbolAddress((void**)&kl,  g_kl);
    cudaGetSymbolAddress((void**)&vth, g_vth);
    cudaGetSymbolAddress((void**)&vtl, g_vtl);

    const size_t W3SZ = (size_t)DMODEL * KX;

    conv_expand<<<(M_TOT*512)/256, 256>>>(x,  x3, 1);
    conv_expand<<<(DMODEL*512)/256, 256>>>(wq, w3 + 0*W3SZ, 0);
    conv_expand<<<(DMODEL*512)/256, 256>>>(wk, w3 + 1*W3SZ, 0);
    conv_expand<<<(DMODEL*512)/256, 256>>>(wv, w3 + 2*W3SZ, 0);
    conv_expand<<<(DMODEL*512)/256, 256>>>(wo, w3 + 3*W3SZ, 0);

    cudaFuncSetAttribute(gemm_mma, cudaFuncAttributeMaxDynamicSharedMemorySize,
                         (int)GEMM_SMEM);
    // fused QKV: N = 6144 over contiguous wq|wk|wv expansions
    dim3 gqkv(3*DMODEL/128, M_TOT/128);   // (48, 32)
    gemm_mma<<<gqkv, 256, GEMM_SMEM>>>(x3, w3, nullptr, q, k, v);

    int pairs = M_TOT * NHEADS * (DK/2);
    rope_split<<<(pairs + 255) / 256, 256>>>(q, k, qh, ql, kh, kl);
    vt_split<<<dim3(SEQ/64, BATCH*NHEADS), 256>>>(v, vth, vtl);

    cudaFuncSetAttribute(flash_attn_mma, cudaFuncAttributeMaxDynamicSharedMemorySize,
                         (int)ATTN_SMEM);
    dim3 agrid(SEQ/ABQ, BATCH*NHEADS);   // (16, 32)
    flash_attn_mma<<<agrid, 256, ATTN_SMEM>>>(qh, ql, kh, kl, vth, vtl, ao);

    conv_expand<<<(M_TOT*512)/256, 256>>>(ao, ao3, 1);
    dim3 gout(DMODEL/128, M_TOT/128);     // (16, 32)
    gemm_mma<<<gout, 256, GEMM_SMEM>>>(ao3, w3 + 3*W3SZ, bo, out, out, out);
}